// round 2
// baseline (speedup 1.0000x reference)
#include <cuda_runtime.h>
#include <cuda_bf16.h>

// Problem shape (fixed by the dataset):
//   A: [32, 4096, 64] f32, B: [32, 64, 4096] f32, index: [32, 4096, 32] i32
//   C[b,m,t] = sum_k A[b,m,k] * B[b,k,index[b,m,t]]
#define BB   32
#define MDIM 4096
#define KDIM 64
#define NDIM 4096
#define TOPK 32

// 32 MB scratch for the transposed B: Bt[b][n][k] (gathered rows become
// contiguous 256B). __device__ global per allocation rules.
__device__ float g_Bt[(size_t)BB * NDIM * KDIM];

// ---------------------------------------------------------------------------
// Kernel 1: transpose B[b,k,n] -> Bt[b,n,k]. smem-tiled, coalesced both ways.
// grid: (NDIM/32, BB), block: (32, 16)
// ---------------------------------------------------------------------------
__global__ void __launch_bounds__(512) transpose_kernel(const float* __restrict__ B) {
    __shared__ float tile[KDIM][33];   // 64 x 33 floats, padded: conflict-free
    const int b  = blockIdx.y;
    const int n0 = blockIdx.x * 32;
    const int tx = threadIdx.x;        // 0..31  (n within tile)
    const int ty = threadIdx.y;        // 0..15

    const float* Bb = B + (size_t)b * KDIM * NDIM;
    #pragma unroll
    for (int k = ty; k < KDIM; k += 16)
        tile[k][tx] = Bb[(size_t)k * NDIM + n0 + tx];   // coalesced in n
    __syncthreads();

    float* Bt = g_Bt + (size_t)b * NDIM * KDIM;
    const int tid = ty * 32 + tx;      // 0..511
    const int kk  = tid & 63;          // k index
    const int r   = tid >> 6;          // 0..7 (row within write group)
    #pragma unroll
    for (int r0 = 0; r0 < 32; r0 += 8)
        // 8 consecutive 256B rows => 2KB contiguous coalesced writes
        Bt[(size_t)(n0 + r0 + r) * KDIM + kk] = tile[kk][r0 + r];
}

// ---------------------------------------------------------------------------
// Kernel 2: gather + dot. One warp per (b, m).
// Lane layout: g = lane>>3 (4 groups, one t each per chunk), j = lane&7
// (8 lanes cooperatively read one gathered 256B row as 2x float4 each).
// grid: (MDIM/8, BB), block: 256 (8 warps = 8 m-rows)
// ---------------------------------------------------------------------------
__global__ void __launch_bounds__(256) gather_dot_kernel(
    const float* __restrict__ A,
    const int*   __restrict__ index,
    float*       __restrict__ C)
{
    const int warp = threadIdx.x >> 5;
    const int lane = threadIdx.x & 31;
    const int b    = blockIdx.y;
    const int m    = blockIdx.x * 8 + warp;
    const int j    = lane & 7;
    const int g    = lane >> 3;

    // A row for this m: lane j holds floats [8j, 8j+8) (replicated across groups)
    const float4* A4 = reinterpret_cast<const float4*>(A + ((size_t)b * MDIM + m) * KDIM);
    const float4 a0 = __ldg(&A4[2 * j]);
    const float4 a1 = __ldg(&A4[2 * j + 1]);

    // each lane holds the index for t = lane; broadcast per-chunk via shfl
    const int myidx = __ldg(&index[((size_t)b * MDIM + m) * TOPK + lane]);

    const float* BtB  = g_Bt + (size_t)b * NDIM * KDIM;
    float*       Cout = C + ((size_t)b * MDIM + m) * TOPK;

    #pragma unroll
    for (int t0 = 0; t0 < TOPK; t0 += 4) {
        const int idxv = __shfl_sync(0xffffffffu, myidx, t0 + g);
        const float4* r4 = reinterpret_cast<const float4*>(BtB + (size_t)idxv * KDIM);
        const float4 b0 = r4[2 * j];        // group reads contiguous 256B row
        const float4 b1 = r4[2 * j + 1];

        float p = a0.x * b0.x + a0.y * b0.y + a0.z * b0.z + a0.w * b0.w
                + a1.x * b1.x + a1.y * b1.y + a1.z * b1.z + a1.w * b1.w;

        // reduce over the 8 lanes of each group (xor keeps it intra-group)
        p += __shfl_xor_sync(0xffffffffu, p, 1);
        p += __shfl_xor_sync(0xffffffffu, p, 2);
        p += __shfl_xor_sync(0xffffffffu, p, 4);

        if (j == 0) Cout[t0 + g] = p;       // lanes 0,8,16,24 -> 16B contiguous
    }
}

// ---------------------------------------------------------------------------
extern "C" void kernel_launch(void* const* d_in, const int* in_sizes, int n_in,
                              void* d_out, int out_size) {
    const float* A   = (const float*)d_in[0];
    const float* B   = (const float*)d_in[1];
    const int*   idx = (const int*)d_in[2];
    float*       C   = (float*)d_out;

    transpose_kernel<<<dim3(NDIM / 32, BB), dim3(32, 16)>>>(B);
    gather_dot_kernel<<<dim3(MDIM / 8, BB), 256>>>(A, idx, C);
}

// round 5
// speedup vs baseline: 1.5160x; 1.5160x over previous
#include <cuda_runtime.h>
#include <cuda_fp16.h>

// Problem shape (fixed by the dataset):
//   A: [32, 4096, 64] f32, B: [32, 64, 4096] f32, index: [32, 4096, 32] i32
//   C[b,m,t] = sum_k A[b,m,k] * B[b,k,index[b,m,t]]
#define BB   32
#define MDIM 4096
#define KDIM 64
#define NDIM 4096
#define TOPK 32

// 16 MB scratch: transposed B in fp16. Bt16[b][n][k] — one gathered row is
// 64 halves = 128 B = exactly one L1 line (1 wavefront per gather group).
__device__ __half2 g_Bt16[(size_t)BB * NDIM * (KDIM / 2)];

// ---------------------------------------------------------------------------
// Kernel 1: transpose+convert B[b,k,n] f32 -> Bt16[b,n,k] fp16.
// grid: (NDIM/32, BB), block: (32, 16)
// ---------------------------------------------------------------------------
__global__ void __launch_bounds__(512) transpose_kernel(const float* __restrict__ B) {
    __shared__ float tile[KDIM][33];   // 64 x 33 floats, padded: conflict-free
    const int b  = blockIdx.y;
    const int n0 = blockIdx.x * 32;
    const int tx = threadIdx.x;        // 0..31  (n within tile)
    const int ty = threadIdx.y;        // 0..15

    const float* Bb = B + (size_t)b * KDIM * NDIM;
    #pragma unroll
    for (int k = ty; k < KDIM; k += 16)
        tile[k][tx] = Bb[(size_t)k * NDIM + n0 + tx];   // coalesced in n
    __syncthreads();

    __half2* Bt = g_Bt16 + (size_t)b * NDIM * (KDIM / 2);
    const int tid = ty * 32 + tx;      // 0..511
    const int h   = tid & 31;          // half2 index within row (k = 2h, 2h+1)
    const int r   = tid >> 5;          // 0..15 (row within tile)
    #pragma unroll
    for (int r0 = 0; r0 < 32; r0 += 16) {
        const int row = r0 + r;
        // 16 consecutive 128B rows => 2KB contiguous coalesced writes
        Bt[(size_t)(n0 + row) * 32 + h] =
            __floats2half2_rn(tile[2 * h][row], tile[2 * h + 1][row]);
    }
}

// ---------------------------------------------------------------------------
// Kernel 2: gather + dot. One warp per (b, m).
// Lane layout: g = lane>>3 (4 groups, one t each per chunk), j = lane&7
// (8 lanes cooperatively read one gathered 128B fp16 row: 1 LDG.128 each).
// grid: (MDIM/8, BB), block: 256 (8 warps = 8 m-rows)
// ---------------------------------------------------------------------------
__global__ void __launch_bounds__(256) gather_dot_kernel(
    const float* __restrict__ A,
    const int*   __restrict__ index,
    float*       __restrict__ C)
{
    const int warp = threadIdx.x >> 5;
    const int lane = threadIdx.x & 31;
    const int b    = blockIdx.y;
    const int m    = blockIdx.x * 8 + warp;
    const int j    = lane & 7;
    const int g    = lane >> 3;

    // A row for this m: lane j holds floats [8j, 8j+8) (replicated across groups)
    const float4* A4 = reinterpret_cast<const float4*>(A + ((size_t)b * MDIM + m) * KDIM);
    const float4 a0 = __ldg(&A4[2 * j]);
    const float4 a1 = __ldg(&A4[2 * j + 1]);

    // each lane holds the index for t = lane; broadcast per-chunk via shfl
    const int myidx = __ldg(&index[((size_t)b * MDIM + m) * TOPK + lane]);

    const __half2* BtB = g_Bt16 + (size_t)b * NDIM * (KDIM / 2);
    float* __restrict__ Cout = C + ((size_t)b * MDIM + m) * TOPK;

    #pragma unroll
    for (int t0 = 0; t0 < TOPK; t0 += 4) {
        const int idxv = __shfl_sync(0xffffffffu, myidx, t0 + g);
        // gathered row = 128 B; lane j reads its 16B slice (8 halves)
        const uint4 bv = __ldg(&reinterpret_cast<const uint4*>(BtB + (size_t)idxv * 32)[j]);

        const float2 f0 = __half22float2(*reinterpret_cast<const __half2*>(&bv.x));
        const float2 f1 = __half22float2(*reinterpret_cast<const __half2*>(&bv.y));
        const float2 f2 = __half22float2(*reinterpret_cast<const __half2*>(&bv.z));
        const float2 f3 = __half22float2(*reinterpret_cast<const __half2*>(&bv.w));

        float p = a0.x * f0.x + a0.y * f0.y + a0.z * f1.x + a0.w * f1.y
                + a1.x * f2.x + a1.y * f2.y + a1.z * f3.x + a1.w * f3.y;

        // reduce over the 8 lanes of each group (xor keeps it intra-group)
        p += __shfl_xor_sync(0xffffffffu, p, 1);
        p += __shfl_xor_sync(0xffffffffu, p, 2);
        p += __shfl_xor_sync(0xffffffffu, p, 4);

        if (j == 0) Cout[t0 + g] = p;       // lanes 0,8,16,24 -> 16B contiguous
    }
}

// ---------------------------------------------------------------------------
extern "C" void kernel_launch(void* const* d_in, const int* in_sizes, int n_in,
                              void* d_out, int out_size) {
    const float* A   = (const float*)d_in[0];
    const float* B   = (const float*)d_in[1];
    const int*   idx = (const int*)d_in[2];
    float*       C   = (float*)d_out;

    transpose_kernel<<<dim3(NDIM / 32, BB), dim3(32, 16)>>>(B);
    gather_dot_kernel<<<dim3(MDIM / 8, BB), 256>>>(A, idx, C);
}

// round 7
// speedup vs baseline: 1.6966x; 1.1191x over previous
#include <cuda_runtime.h>
#include <cuda_fp16.h>

// Problem shape (fixed by the dataset):
//   A: [32, 4096, 64] f32, B: [32, 64, 4096] f32, index: [32, 4096, 32] i32
//   C[b,m,t] = sum_k A[b,m,k] * B[b,k,index[b,m,t]]
#define BB   32
#define MDIM 4096
#define KDIM 64
#define NDIM 4096
#define TOPK 32
#define NTILE 64

// 16 MB scratch: transposed B in fp16. Bt16[b][n][k] — one gathered row is
// 64 halves = 128 B = exactly one L1 line (1 wavefront per gather group).
__device__ __half2 g_Bt16[(size_t)BB * NDIM * (KDIM / 2)];

// ---------------------------------------------------------------------------
// Kernel 1: transpose+convert B[b,k,n] f32 -> Bt16[b,n,k] fp16.
// 64x64 tiles; each thread emits one 16B (8-half) chunk via STG.128.
// grid: (NDIM/64, BB), block: (32, 16)
// ---------------------------------------------------------------------------
__global__ void __launch_bounds__(512) transpose_kernel(const float* __restrict__ B) {
    __shared__ float tile[KDIM][NTILE + 1];   // 64 x 65 floats
    const int b  = blockIdx.y;
    const int n0 = blockIdx.x * NTILE;
    const int tx = threadIdx.x;        // 0..31
    const int ty = threadIdx.y;        // 0..15

    const float* Bb = B + (size_t)b * KDIM * NDIM;
    #pragma unroll
    for (int k = ty; k < KDIM; k += 16) {
        tile[k][tx]      = Bb[(size_t)k * NDIM + n0 + tx];        // coalesced
        tile[k][tx + 32] = Bb[(size_t)k * NDIM + n0 + tx + 32];
    }
    __syncthreads();

    const int tid = ty * 32 + tx;      // 0..511
    const int row = tid >> 3;          // 0..63  (n within tile)
    const int c   = tid & 7;           // 16B chunk: k = 8c..8c+7
    uint4 out;
    __half2* o2 = reinterpret_cast<__half2*>(&out);
    #pragma unroll
    for (int i = 0; i < 4; i++)
        o2[i] = __floats2half2_rn(tile[8 * c + 2 * i][row], tile[8 * c + 2 * i + 1][row]);

    // warp writes 4 consecutive 128B rows = 512B contiguous
    __half2* dst = g_Bt16 + (size_t)b * NDIM * 32 + (size_t)(n0 + row) * 32;
    reinterpret_cast<uint4*>(dst)[c] = out;
}

// ---------------------------------------------------------------------------
// Kernel 2: gather + dot. One warp per (b, m).
// Lane layout: g = lane>>3 (4 groups, one t each per chunk), j = lane&7
// (8 lanes cooperatively read one gathered 128B fp16 row: 1 LDG.128 each).
// Inner product in half2 (HFMA2 chain), promoted to f32 before cross-lane
// reduction. grid: (MDIM/8, BB), block: 256 (8 warps = 8 m-rows)
// ---------------------------------------------------------------------------
__global__ void __launch_bounds__(256, 6) gather_dot_kernel(
    const float* __restrict__ A,
    const int*   __restrict__ index,
    float*       __restrict__ C)
{
    const int warp = threadIdx.x >> 5;
    const int lane = threadIdx.x & 31;
    const int b    = blockIdx.y;
    const int m    = blockIdx.x * 8 + warp;
    const int j    = lane & 7;
    const int g    = lane >> 3;

    // A row for this m: lane j holds floats [8j, 8j+8), converted to half2 once
    const float4* A4 = reinterpret_cast<const float4*>(A + ((size_t)b * MDIM + m) * KDIM);
    const float4 a0 = __ldg(&A4[2 * j]);
    const float4 a1 = __ldg(&A4[2 * j + 1]);
    const __half2 ah0 = __floats2half2_rn(a0.x, a0.y);
    const __half2 ah1 = __floats2half2_rn(a0.z, a0.w);
    const __half2 ah2 = __floats2half2_rn(a1.x, a1.y);
    const __half2 ah3 = __floats2half2_rn(a1.z, a1.w);

    // each lane holds the index for t = lane; broadcast per-chunk via shfl
    const int myidx = __ldg(&index[((size_t)b * MDIM + m) * TOPK + lane]);

    const __half2* BtB = g_Bt16 + (size_t)b * NDIM * (KDIM / 2);
    float* __restrict__ Cout = C + ((size_t)b * MDIM + m) * TOPK;

    #pragma unroll
    for (int t0 = 0; t0 < TOPK; t0 += 4) {
        const int idxv = __shfl_sync(0xffffffffu, myidx, t0 + g);
        // gathered row = 128 B; lane j reads its 16B slice (8 halves)
        const uint4 bv = __ldg(&reinterpret_cast<const uint4*>(BtB + (size_t)idxv * 32)[j]);

        __half2 acc =       __hmul2(ah0, *reinterpret_cast<const __half2*>(&bv.x));
        acc = __hfma2(ah1, *reinterpret_cast<const __half2*>(&bv.y), acc);
        acc = __hfma2(ah2, *reinterpret_cast<const __half2*>(&bv.z), acc);
        acc = __hfma2(ah3, *reinterpret_cast<const __half2*>(&bv.w), acc);

        const float2 f = __half22float2(acc);
        float p = f.x + f.y;

        // reduce over the 8 lanes of each group (xor keeps it intra-group), f32
        p += __shfl_xor_sync(0xffffffffu, p, 1);
        p += __shfl_xor_sync(0xffffffffu, p, 2);
        p += __shfl_xor_sync(0xffffffffu, p, 4);

        if (j == 0) Cout[t0 + g] = p;       // lanes 0,8,16,24 -> 16B contiguous
    }
}

// ---------------------------------------------------------------------------
extern "C" void kernel_launch(void* const* d_in, const int* in_sizes, int n_in,
                              void* d_out, int out_size) {
    const float* A   = (const float*)d_in[0];
    const float* B   = (const float*)d_in[1];
    const int*   idx = (const int*)d_in[2];
    float*       C   = (float*)d_out;

    transpose_kernel<<<dim3(NDIM / NTILE, BB), dim3(32, 16)>>>(B);
    gather_dot_kernel<<<dim3(MDIM / 8, BB), 256>>>(A, idx, C);
}

// round 8
// speedup vs baseline: 1.7529x; 1.0332x over previous
#include <cuda_runtime.h>
#include <cuda_fp16.h>

// Problem shape (fixed by the dataset):
//   A: [32, 4096, 64] f32, B: [32, 64, 4096] f32, index: [32, 4096, 32] i32
//   C[b,m,t] = sum_k A[b,m,k] * B[b,k,index[b,m,t]]
#define BB   32
#define MDIM 4096
#define KDIM 64
#define NDIM 4096
#define TOPK 32
#define NTILE 64
#define MPW  4            // m-rows per warp
#define MPB  32           // m-rows per block (8 warps * 4)

// 16 MB scratch: transposed B in fp16. Bt16[b][n][k] — one gathered row is
// 64 halves = 128 B = exactly one L1 line (1 wavefront per gather group).
__device__ __half2 g_Bt16[(size_t)BB * NDIM * (KDIM / 2)];

// ---------------------------------------------------------------------------
// Kernel 1: transpose+convert B[b,k,n] f32 -> Bt16[b,n,k] fp16.
// 64x64 tiles; each thread emits one 16B (8-half) chunk via STG.128.
// grid: (NDIM/64, BB), block: (32, 16)
// ---------------------------------------------------------------------------
__global__ void __launch_bounds__(512) transpose_kernel(const float* __restrict__ B) {
    __shared__ float tile[KDIM][NTILE + 1];   // 64 x 65 floats
    const int b  = blockIdx.y;
    const int n0 = blockIdx.x * NTILE;
    const int tx = threadIdx.x;        // 0..31
    const int ty = threadIdx.y;        // 0..15

    const float* Bb = B + (size_t)b * KDIM * NDIM;
    #pragma unroll
    for (int k = ty; k < KDIM; k += 16) {
        tile[k][tx]      = Bb[(size_t)k * NDIM + n0 + tx];        // coalesced
        tile[k][tx + 32] = Bb[(size_t)k * NDIM + n0 + tx + 32];
    }
    __syncthreads();

    const int tid = ty * 32 + tx;      // 0..511
    const int row = tid >> 3;          // 0..63  (n within tile)
    const int c   = tid & 7;           // 16B chunk: k = 8c..8c+7
    uint4 out;
    __half2* o2 = reinterpret_cast<__half2*>(&out);
    #pragma unroll
    for (int i = 0; i < 4; i++)
        o2[i] = __floats2half2_rn(tile[8 * c + 2 * i][row], tile[8 * c + 2 * i + 1][row]);

    // warp writes 4 consecutive 128B rows = 512B contiguous
    __half2* dst = g_Bt16 + (size_t)b * NDIM * 32 + (size_t)(n0 + row) * 32;
    reinterpret_cast<uint4*>(dst)[c] = out;
}

// ---------------------------------------------------------------------------
// Kernel 2: gather + dot. One warp per 4 m-rows (looped), block covers 32 m.
// Lane layout: g = lane>>3 (4 groups, one t each per chunk), j = lane&7
// (8 lanes cooperatively read one gathered 128B fp16 row: 1 LDG.128 each).
// Inner product in half2 (HFMA2), f32 cross-lane reduce; results staged in
// smem, then one contiguous 4KB block store (1 store wavefront per warp).
// grid: (MDIM/32, BB), block: 256
// ---------------------------------------------------------------------------
__global__ void __launch_bounds__(256, 6) gather_dot_kernel(
    const float* __restrict__ A,
    const int*   __restrict__ index,
    float*       __restrict__ C)
{
    __shared__ float sres[MPB][TOPK];   // 4 KB, [m_local][t]

    const int warp = threadIdx.x >> 5;
    const int lane = threadIdx.x & 31;
    const int b    = blockIdx.y;
    const int j    = lane & 7;
    const int g    = lane >> 3;

    const int m0 = blockIdx.x * MPB + warp * MPW;   // first m of this warp
    const __half2* BtB = g_Bt16 + (size_t)b * NDIM * (KDIM / 2);

    #pragma unroll 1
    for (int mi = 0; mi < MPW; mi++) {
        const int m = m0 + mi;

        // A row: lane j holds floats [8j, 8j+8), converted to half2 once
        const float4* A4 = reinterpret_cast<const float4*>(A + ((size_t)b * MDIM + m) * KDIM);
        const float4 a0 = __ldg(&A4[2 * j]);
        const float4 a1 = __ldg(&A4[2 * j + 1]);
        const __half2 ah0 = __floats2half2_rn(a0.x, a0.y);
        const __half2 ah1 = __floats2half2_rn(a0.z, a0.w);
        const __half2 ah2 = __floats2half2_rn(a1.x, a1.y);
        const __half2 ah3 = __floats2half2_rn(a1.z, a1.w);

        // lane t holds index for t; broadcast per chunk via shfl
        const int myidx = __ldg(&index[((size_t)b * MDIM + m) * TOPK + lane]);

        float* srow = sres[warp * MPW + mi];

        #pragma unroll
        for (int t0 = 0; t0 < TOPK; t0 += 4) {
            const int idxv = __shfl_sync(0xffffffffu, myidx, t0 + g);
            // gathered row = 128 B; lane j reads its 16B slice (8 halves)
            const uint4 bv = __ldg(&reinterpret_cast<const uint4*>(BtB + (size_t)idxv * 32)[j]);

            __half2 acc =       __hmul2(ah0, *reinterpret_cast<const __half2*>(&bv.x));
            acc = __hfma2(ah1, *reinterpret_cast<const __half2*>(&bv.y), acc);
            acc = __hfma2(ah2, *reinterpret_cast<const __half2*>(&bv.z), acc);
            acc = __hfma2(ah3, *reinterpret_cast<const __half2*>(&bv.w), acc);

            const float2 f = __half22float2(acc);
            float p = f.x + f.y;

            // reduce over the 8 lanes of each group (xor keeps it intra-group)
            p += __shfl_xor_sync(0xffffffffu, p, 1);
            p += __shfl_xor_sync(0xffffffffu, p, 2);
            p += __shfl_xor_sync(0xffffffffu, p, 4);

            if (j == 0) srow[t0 + g] = p;   // 4 lanes, 4 consecutive banks
        }
    }
    __syncthreads();

    // Block's C chunk is 32 m x 32 t = 4KB contiguous: one STG.128 per thread.
    float4* dst = reinterpret_cast<float4*>(
        C + ((size_t)b * MDIM + (size_t)blockIdx.x * MPB) * TOPK);
    dst[threadIdx.x] = reinterpret_cast<const float4*>(sres)[threadIdx.x];
}

// ---------------------------------------------------------------------------
extern "C" void kernel_launch(void* const* d_in, const int* in_sizes, int n_in,
                              void* d_out, int out_size) {
    const float* A   = (const float*)d_in[0];
    const float* B   = (const float*)d_in[1];
    const int*   idx = (const int*)d_in[2];
    float*       C   = (float*)d_out;

    transpose_kernel<<<dim3(NDIM / NTILE, BB), dim3(32, 16)>>>(B);
    gather_dot_kernel<<<dim3(MDIM / MPB, BB), 256>>>(A, idx, C);
}